// round 5
// baseline (speedup 1.0000x reference)
#include <cuda_runtime.h>
#include <cuda_bf16.h>

#define N_NEURON 128
#define N_RULES  512
#define BATCH    4096
#define HALF_N   (N_NEURON / 2)

// Two warps per batch element (each covers 64 neurons), combined via smem.
// block = 128 threads = 4 warps = 2 batch elements x 2 neuron-halves.
__global__ void __launch_bounds__(128, 10) lei_fused2_kernel(
    const float* __restrict__ x,
    const float* __restrict__ head_w,
    const float* __restrict__ head_b,
    const float* __restrict__ foot_w,
    const float* __restrict__ foot_b,
    float* __restrict__ out)
{
    const int warp = threadIdx.x >> 5;
    const int lane = threadIdx.x & 31;
    const int bl   = warp & 1;    // which of the 2 batch elements in this CTA
    const int half = warp >> 1;   // which neuron half [half*64, half*64+64)
    const int b = blockIdx.x * 2 + bl;

    __shared__ float s0[2], s1[2];

    const float* __restrict__ fw0 = foot_w;            // [128]
    const float* __restrict__ fw1 = foot_w + N_NEURON; // [128]

    float acc0 = 0.0f, acc1 = 0.0f;

    // Fold head-bias contribution for this warp's neuron half.
#pragma unroll
    for (int k = 0; k < 2; k++) {
        int n = half * HALF_N + 32 * k + lane;
        float hb = head_b[n];
        acc0 = fmaf(hb, fw0[n], acc0);
        acc1 = fmaf(hb, fw1[n], acc1);
    }

    const size_t nstride = (size_t)BATCH * (N_RULES / 4);  // float4 stride between neurons
    const float4* __restrict__ xp =
        reinterpret_cast<const float4*>(x)
        + (size_t)(half * HALF_N) * nstride + (size_t)b * (N_RULES / 4) + lane;
    const float4* __restrict__ wp =
        reinterpret_cast<const float4*>(head_w)
        + (size_t)(half * HALF_N) * (N_RULES / 4) + lane;

    const int n_begin = half * HALF_N;
#pragma unroll 2
    for (int i = 0; i < HALF_N; i++) {
        float4 xv[4];
#pragma unroll
        for (int k = 0; k < 4; k++) xv[k] = __ldcs(xp + 32 * k);
        xp += nstride;

        float pa = 0.0f;
#pragma unroll
        for (int k = 0; k < 4; k++) {
            float4 wv = wp[32 * k];
            pa = fmaf(xv[k].x, wv.x, pa);
            pa = fmaf(xv[k].y, wv.y, pa);
            pa = fmaf(xv[k].z, wv.z, pa);
            pa = fmaf(xv[k].w, wv.w, pa);
        }
        wp += N_RULES / 4;

        const int n = n_begin + i;
        acc0 = fmaf(pa, fw0[n], acc0);
        acc1 = fmaf(pa, fw1[n], acc1);
    }

    // Warp reduction of the two partial logit accumulators.
#pragma unroll
    for (int off = 16; off; off >>= 1) {
        acc0 += __shfl_xor_sync(0xFFFFFFFFu, acc0, off);
        acc1 += __shfl_xor_sync(0xFFFFFFFFu, acc1, off);
    }

    // Combine the two neuron-halves through smem.
    if (half == 1 && lane == 0) {
        s0[bl] = acc0;
        s1[bl] = acc1;
    }
    __syncthreads();

    if (half == 0 && lane == 0) {
        float l0 = acc0 + s0[bl] + foot_b[0];
        float l1 = acc1 + s1[bl] + foot_b[1];
        float m = fmaxf(l0, l1);
        float e0 = __expf(l0 - m);
        float e1 = __expf(l1 - m);
        float inv = 1.0f / (e0 + e1);
        out[b * 2 + 0] = e0 * inv;
        out[b * 2 + 1] = e1 * inv;
    }
}

extern "C" void kernel_launch(void* const* d_in, const int* in_sizes, int n_in,
                              void* d_out, int out_size)
{
    const float* x      = (const float*)d_in[0];
    const float* head_w = (const float*)d_in[1];
    const float* head_b = (const float*)d_in[2];
    const float* foot_w = (const float*)d_in[3];
    const float* foot_b = (const float*)d_in[4];
    float* out = (float*)d_out;

    // 8192 warps total: 2048 blocks x 128 threads (2 b's per block).
    lei_fused2_kernel<<<BATCH / 2, 128>>>(x, head_w, head_b, foot_w, foot_b, out);
}